// round 5
// baseline (speedup 1.0000x reference)
#include <cuda_runtime.h>
#include <cuda_fp16.h>

#define NN 50000
#define NE 800000
#define HEADS 8
#define H1DIM 128
#define OUTC 40
#define NEG 0.2f
#define NB_SCAN 200          // 200 blocks x 250 nodes

// ---------------- scratch ----------------
__device__ __align__(16) __half2 g_h1h[NN * 64];   // layer1 features fp16
__device__ float g_as1[NN * HEADS];
__device__ float g_ad1[NN * HEADS];
__device__ float g_out1[NN * H1DIM];
__device__ __align__(8) __half g_h2h[NN * OUTC];   // layer2 features fp16
__device__ float g_as2[NN];
__device__ float g_ad2[NN];
__device__ int   g_deg[NN];
__device__ int   g_off[NN];            // local-block exclusive scan; scatter bumps to local end
__device__ int   g_base[NB_SCAN];      // global base per scan block
__device__ int   g_part[NB_SCAN];
__device__ int   g_csrc[NE];

__device__ __forceinline__ float leaky(float v) { return v > 0.f ? v : NEG * v; }

__device__ __forceinline__ unsigned long long pack2(float x, float y) {
    unsigned long long r;
    asm("mov.b64 %0, {%1, %2};" : "=l"(r) : "f"(x), "f"(y));
    return r;
}
__device__ __forceinline__ void unpack2(unsigned long long v, float& x, float& y) {
    asm("mov.b64 {%0, %1}, %2;" : "=f"(x), "=f"(y) : "l"(v));
}
__device__ __forceinline__ void ffma2(unsigned long long& d, unsigned long long a, unsigned long long b) {
    asm("fma.rn.f32x2 %0, %1, %2, %0;" : "+l"(d) : "l"(a), "l"(b));
}

// ---------------- init ----------------
__global__ void k_init() {
    int i = blockIdx.x * blockDim.x + threadIdx.x;
    if (i < NN) g_deg[i] = 0;
}

// ---------------- CSR build ----------------
__global__ void k_deg(const int* __restrict__ ei) {
    int t = blockIdx.x * blockDim.x + threadIdx.x;
    if (t * 4 >= NE) return;
    int4 d4 = *(const int4*)&ei[NE + t * 4];
    atomicAdd(&g_deg[d4.x], 1);
    atomicAdd(&g_deg[d4.y], 1);
    atomicAdd(&g_deg[d4.z], 1);
    atomicAdd(&g_deg[d4.w], 1);
}

__global__ void k_scan1() {
    __shared__ int sm[256];
    int b = blockIdx.x, t = threadIdx.x;
    int n = b * 250 + t;
    int v = (t < 250 && n < NN) ? g_deg[n] : 0;
    sm[t] = v;
    __syncthreads();
#pragma unroll
    for (int o = 1; o < 256; o <<= 1) {
        int u = (t >= o) ? sm[t - o] : 0;
        __syncthreads();
        sm[t] += u;
        __syncthreads();
    }
    if (t < 250 && n < NN) g_off[n] = sm[t] - v;
    if (t == 255) g_part[b] = sm[255];
}

__global__ void k_scan2() {
    __shared__ int sm[256];
    int t = threadIdx.x;
    int v = (t < NB_SCAN) ? g_part[t] : 0;
    sm[t] = v;
    __syncthreads();
#pragma unroll
    for (int o = 1; o < 256; o <<= 1) {
        int u = (t >= o) ? sm[t - o] : 0;
        __syncthreads();
        sm[t] += u;
        __syncthreads();
    }
    if (t < NB_SCAN) g_base[t] = sm[t] - v;
}

__global__ void k_scatter(const int* __restrict__ ei) {
    int t = blockIdx.x * blockDim.x + threadIdx.x;
    if (t * 4 >= NE) return;
    int4 s4 = *(const int4*)&ei[t * 4];
    int4 d4 = *(const int4*)&ei[NE + t * 4];
    int p;
    p = atomicAdd(&g_off[d4.x], 1) + g_base[d4.x / 250]; g_csrc[p] = s4.x;
    p = atomicAdd(&g_off[d4.y], 1) + g_base[d4.y / 250]; g_csrc[p] = s4.y;
    p = atomicAdd(&g_off[d4.z], 1) + g_base[d4.z / 250]; g_csrc[p] = s4.z;
    p = atomicAdd(&g_off[d4.w], 1) + g_base[d4.w / 250]; g_csrc[p] = s4.w;
}

__device__ __forceinline__ int node_end(int n) {
    return g_off[n] + g_base[n / 250];
}

// ---------------- GEMM1: h1 = x @ W1, packed f32x2 FMA, fp16 store + logits -----
__global__ void k_gemm1(const float* __restrict__ A, const float* __restrict__ B,
                        const float* __restrict__ att_src, const float* __restrict__ att_dst) {
    __shared__ float As[16][128];
    __shared__ float Bs[16][128];
    int tid = threadIdx.x;
    int tx = tid & 15;
    int ty = tid >> 4;
    int row0 = blockIdx.x * 128;
    unsigned long long acc[8][4];
#pragma unroll
    for (int i = 0; i < 8; i++)
#pragma unroll
        for (int j = 0; j < 4; j++) acc[i][j] = pack2(0.f, 0.f);
    for (int k0 = 0; k0 < 128; k0 += 16) {
#pragma unroll
        for (int p = 0; p < 2; p++) {
            int fi = tid + p * 256;
            int r = fi >> 2;
            int kk = (fi & 3) * 4;
            int grow = row0 + r;
            float4 v = make_float4(0.f, 0.f, 0.f, 0.f);
            if (grow < NN) v = *(const float4*)&A[grow * 128 + k0 + kk];
            As[kk + 0][r] = v.x; As[kk + 1][r] = v.y;
            As[kk + 2][r] = v.z; As[kk + 3][r] = v.w;
        }
#pragma unroll
        for (int p = 0; p < 2; p++) {
            int fi = tid + p * 256;
            int kk = fi >> 5;
            int nc = (fi & 31) * 4;
            *(float4*)&Bs[kk][nc] = *(const float4*)&B[(k0 + kk) * 128 + nc];
        }
        __syncthreads();
#pragma unroll
        for (int kk = 0; kk < 16; kk++) {
            float a[8];
#pragma unroll
            for (int i = 0; i < 8; i++) a[i] = As[kk][ty * 8 + i];
            ulonglong2 b01 = *(const ulonglong2*)&Bs[kk][tx * 8];
            ulonglong2 b23 = *(const ulonglong2*)&Bs[kk][tx * 8 + 4];
            unsigned long long bb[4] = {b01.x, b01.y, b23.x, b23.y};
#pragma unroll
            for (int i = 0; i < 8; i++) {
                unsigned long long aa = pack2(a[i], a[i]);
#pragma unroll
                for (int j = 0; j < 4; j++) ffma2(acc[i][j], aa, bb[j]);
            }
        }
        __syncthreads();
    }
    float ws[8], wd[8];
#pragma unroll
    for (int j = 0; j < 8; j++) { ws[j] = att_src[tx * 8 + j]; wd[j] = att_dst[tx * 8 + j]; }
#pragma unroll
    for (int i = 0; i < 8; i++) {
        float af[8];
#pragma unroll
        for (int j = 0; j < 4; j++) unpack2(acc[i][j], af[2 * j], af[2 * j + 1]);
        int grow = row0 + ty * 8 + i;
        float ps = 0.f, pd = 0.f;
#pragma unroll
        for (int j = 0; j < 8; j++) { ps += af[j] * ws[j]; pd += af[j] * wd[j]; }
        if (grow < NN) {
            __half2 hh[4];
#pragma unroll
            for (int q = 0; q < 4; q++)
                hh[q] = __floats2half2_rn(af[q * 2], af[q * 2 + 1]);
            *(uint4*)&g_h1h[grow * 64 + tx * 4] = *(uint4*)hh;
        }
        ps += __shfl_xor_sync(0xffffffffu, ps, 1);
        pd += __shfl_xor_sync(0xffffffffu, pd, 1);
        if ((tx & 1) == 0 && grow < NN) {
            g_as1[grow * 8 + (tx >> 1)] = ps;
            g_ad1[grow * 8 + (tx >> 1)] = pd;
        }
    }
}

// ---------------- layer1 node kernel ----------------
__global__ void k_node1(const float* __restrict__ b1) {
    int lane = threadIdx.x & 31;
    int warp = (blockIdx.x * blockDim.x + threadIdx.x) >> 5;
    int nwarp = (gridDim.x * blockDim.x) >> 5;
    int h = lane >> 2;
    for (int n = warp; n < NN; n += nwarp) {
        int beg = (n == 0) ? 0 : node_end(n - 1);
        int end = node_end(n);
        float ad = g_ad1[n * 8 + h];
        float4 acc = make_float4(0.f, 0.f, 0.f, 0.f);
        float sum = 0.f;
        for (int base = beg; base < end; base += 32) {
            int cnt = end - base; if (cnt > 32) cnt = 32;
            int idx = (lane < cnt) ? g_csrc[base + lane] : 0;
#pragma unroll 4
            for (int j = 0; j < cnt; j++) {
                int s = __shfl_sync(0xffffffffu, idx, j);
                float e = __expf(leaky(g_as1[s * 8 + h] + ad));
                sum += e;
                uint2 raw = *(const uint2*)&g_h1h[s * 64 + lane * 2];
                float2 f0 = __half22float2(((const __half2*)&raw)[0]);
                float2 f1 = __half22float2(((const __half2*)&raw)[1]);
                acc.x += e * f0.x; acc.y += e * f0.y;
                acc.z += e * f1.x; acc.w += e * f1.y;
            }
        }
        float inv = (sum > 0.f) ? 1.f / sum : 0.f;
        float4 bv = *(const float4*)&b1[lane * 4];
        float4 o;
        o.x = acc.x * inv + bv.x; o.y = acc.y * inv + bv.y;
        o.z = acc.z * inv + bv.z; o.w = acc.w * inv + bv.w;
        o.x = o.x > 0.f ? o.x : expm1f(o.x);
        o.y = o.y > 0.f ? o.y : expm1f(o.y);
        o.z = o.z > 0.f ? o.z : expm1f(o.z);
        o.w = o.w > 0.f ? o.w : expm1f(o.w);
        *(float4*)&g_out1[n * 128 + lane * 4] = o;
    }
}

// ---------------- GEMM2: h2 = out1 @ W2 (fp16 store) + logits ----------------
__global__ void k_gemm2(const float* __restrict__ B,
                        const float* __restrict__ att_src, const float* __restrict__ att_dst) {
    __shared__ float As[16][128];
    __shared__ float Bs[16][40];
    int tid = threadIdx.x;
    int tx = tid & 7;
    int ty = tid >> 3;
    int row0 = blockIdx.x * 128;
    float acc[4][5] = {};
    for (int k0 = 0; k0 < 128; k0 += 16) {
#pragma unroll
        for (int p = 0; p < 2; p++) {
            int fi = tid + p * 256;
            int r = fi >> 2;
            int kk = (fi & 3) * 4;
            int grow = row0 + r;
            float4 v = make_float4(0.f, 0.f, 0.f, 0.f);
            if (grow < NN) v = *(const float4*)&g_out1[grow * 128 + k0 + kk];
            As[kk + 0][r] = v.x; As[kk + 1][r] = v.y;
            As[kk + 2][r] = v.z; As[kk + 3][r] = v.w;
        }
        if (tid < 160) {
            int kk = tid / 10;
            int nc = (tid % 10) * 4;
            *(float4*)&Bs[kk][nc] = *(const float4*)&B[(k0 + kk) * 40 + nc];
        }
        __syncthreads();
#pragma unroll
        for (int kk = 0; kk < 16; kk++) {
            float a[4], b[5];
#pragma unroll
            for (int i = 0; i < 4; i++) a[i] = As[kk][ty * 4 + i];
#pragma unroll
            for (int j = 0; j < 5; j++) b[j] = Bs[kk][tx * 5 + j];
#pragma unroll
            for (int i = 0; i < 4; i++)
#pragma unroll
                for (int j = 0; j < 5; j++) acc[i][j] += a[i] * b[j];
        }
        __syncthreads();
    }
    float ws[5], wd[5];
#pragma unroll
    for (int j = 0; j < 5; j++) { ws[j] = att_src[tx * 5 + j]; wd[j] = att_dst[tx * 5 + j]; }
#pragma unroll
    for (int i = 0; i < 4; i++) {
        int grow = row0 + ty * 4 + i;
        float ps = 0.f, pd = 0.f;
#pragma unroll
        for (int j = 0; j < 5; j++) {
            ps += acc[i][j] * ws[j];
            pd += acc[i][j] * wd[j];
            if (grow < NN) g_h2h[grow * 40 + tx * 5 + j] = __float2half_rn(acc[i][j]);
        }
        ps += __shfl_xor_sync(0xffffffffu, ps, 1);
        ps += __shfl_xor_sync(0xffffffffu, ps, 2);
        ps += __shfl_xor_sync(0xffffffffu, ps, 4);
        pd += __shfl_xor_sync(0xffffffffu, pd, 1);
        pd += __shfl_xor_sync(0xffffffffu, pd, 2);
        pd += __shfl_xor_sync(0xffffffffu, pd, 4);
        if (tx == 0 && grow < NN) { g_as2[grow] = ps; g_ad2[grow] = pd; }
    }
}

// ---------------- layer2 node kernel → d_out ----------------
__global__ void k_node2(const float* __restrict__ b2, float* __restrict__ dout) {
    int lane = threadIdx.x & 31;
    int warp = (blockIdx.x * blockDim.x + threadIdx.x) >> 5;
    int nwarp = (gridDim.x * blockDim.x) >> 5;
    for (int n = warp; n < NN; n += nwarp) {
        int beg = (n == 0) ? 0 : node_end(n - 1);
        int end = node_end(n);
        float ad = g_ad2[n];
        float4 acc = make_float4(0.f, 0.f, 0.f, 0.f);
        float sum = 0.f;
        for (int base = beg; base < end; base += 32) {
            int cnt = end - base; if (cnt > 32) cnt = 32;
            int idx = (lane < cnt) ? g_csrc[base + lane] : 0;
#pragma unroll 4
            for (int j = 0; j < cnt; j++) {
                int s = __shfl_sync(0xffffffffu, idx, j);
                float e = __expf(leaky(g_as2[s] + ad));
                sum += e;
                if (lane < 10) {
                    uint2 raw = *(const uint2*)&g_h2h[s * 40 + lane * 4];
                    float2 f0 = __half22float2(((const __half2*)&raw)[0]);
                    float2 f1 = __half22float2(((const __half2*)&raw)[1]);
                    acc.x += e * f0.x; acc.y += e * f0.y;
                    acc.z += e * f1.x; acc.w += e * f1.y;
                }
            }
        }
        float inv = (sum > 0.f) ? 1.f / sum : 0.f;
        if (lane < 10) {
            float4 bv = *(const float4*)&b2[lane * 4];
            float4 o;
            o.x = acc.x * inv + bv.x; o.y = acc.y * inv + bv.y;
            o.z = acc.z * inv + bv.z; o.w = acc.w * inv + bv.w;
            *(float4*)&dout[n * 40 + lane * 4] = o;
        }
    }
}

// ---------------- launch ----------------
extern "C" void kernel_launch(void* const* d_in, const int* in_sizes, int n_in,
                              void* d_out, int out_size) {
    const float* x   = (const float*)d_in[0];
    const int*   ei  = (const int*)d_in[1];
    const float* W1  = (const float*)d_in[2];
    const float* as1 = (const float*)d_in[3];
    const float* ad1 = (const float*)d_in[4];
    const float* b1  = (const float*)d_in[5];
    const float* W2  = (const float*)d_in[6];
    const float* as2 = (const float*)d_in[7];
    const float* ad2 = (const float*)d_in[8];
    const float* b2  = (const float*)d_in[9];
    float* out = (float*)d_out;

    k_init<<<(NN + 255) / 256, 256>>>();
    k_deg<<<(NE / 4 + 255) / 256, 256>>>(ei);
    k_scan1<<<NB_SCAN, 256>>>();
    k_scan2<<<1, 256>>>();
    k_scatter<<<(NE / 4 + 255) / 256, 256>>>(ei);
    k_gemm1<<<(NN + 127) / 128, 256>>>(x, W1, as1, ad1);
    k_node1<<<(NN * 32 + 255) / 256, 256>>>(b1);
    k_gemm2<<<(NN + 127) / 128, 256>>>(W2, as2, ad2);
    k_node2<<<(NN * 32 + 255) / 256, 256>>>(b2, out);
}